// round 1
// baseline (speedup 1.0000x reference)
#include <cuda_runtime.h>

#define CC     64
#define KK9    9
#define NH     5
#define NMAX   150000
#define TM     96
#define MAXTILES ((NMAX + TM - 1) / TM)   // 1563
#define BN_EPS 1e-5f

// Scratch (device globals -- no allocations allowed)
__device__ float g_h[(size_t)NH * NMAX * CC];                 // 192 MB intermediate
__device__ float g_part[(size_t)NH * MAXTILES * 2 * CC];      // per-tile sum/sumsq partials
__device__ float g_scale[NH * CC];
__device__ float g_shift[NH * CC];

// ---------------------------------------------------------------------------
// Pass 1: gather-GEMM  h[head, n, o] = sum_k sum_c feat[nbr[n,k], c] * W3[head,k,c,o]
// Tile: 96 voxels x 64 out-channels, K loop = 9 slabs of 64.
// 256 threads, each computes 6 rows x 4 cols. Also emits per-tile BN partials.
// ---------------------------------------------------------------------------
__global__ __launch_bounds__(256) void pass1_kernel(
    const float* __restrict__ feat,
    const int*   __restrict__ nbr,
    const float* __restrict__ W3,
    int Nv, int ntiles)
{
    __shared__ float As[TM][CC + 4];   // gathered tile, pad 4 -> stride 68 (272B, 16B-aligned rows)
    __shared__ float Bs[CC][CC];       // W3[head][k] slab  (reused as reduction buffer after GEMM)
    __shared__ int   sidx[TM];

    const int tid  = threadIdx.x;
    const int tx   = tid & 15;         // 16 col-groups of 4
    const int ty   = tid >> 4;         // 16 row-groups of 6
    const int m0   = blockIdx.x * TM;
    const int head = blockIdx.y;

    float acc[6][4];
    #pragma unroll
    for (int i = 0; i < 6; ++i)
        #pragma unroll
        for (int j = 0; j < 4; ++j) acc[i][j] = 0.f;

    const float* Wh = W3 + (size_t)head * KK9 * CC * CC;

    for (int k = 0; k < KK9; ++k) {
        __syncthreads();   // protect smem from previous iteration's readers

        // neighbor indices for this offset
        if (tid < TM) {
            int m = m0 + tid;
            sidx[tid] = (m < Nv) ? nbr[(size_t)m * KK9 + k] : -1;
        }
        // B slab: 4096 floats, coalesced float4
        {
            const float4* bsrc = (const float4*)(Wh + (size_t)k * CC * CC);
            float4* bdst = (float4*)(&Bs[0][0]);
            #pragma unroll
            for (int w = 0; w < 4; ++w)
                bdst[tid + w * 256] = bsrc[tid + w * 256];
        }
        __syncthreads();

        // A tile: gather rows via sidx; 96 rows x 16 float4
        for (int i = tid; i < TM * (CC / 4); i += 256) {
            int row = i >> 4;
            int c4  = i & 15;
            int idx = sidx[row];
            float4 v = make_float4(0.f, 0.f, 0.f, 0.f);
            if (idx >= 0)
                v = ((const float4*)(feat + (size_t)idx * CC))[c4];
            *(float4*)(&As[row][c4 * 4]) = v;
        }
        __syncthreads();

        // 96x64x64 GEMM slab
        #pragma unroll 8
        for (int kc = 0; kc < CC; ++kc) {
            float4 b = *(const float4*)(&Bs[kc][tx * 4]);
            float a[6];
            #pragma unroll
            for (int i = 0; i < 6; ++i) a[i] = As[ty * 6 + i][kc];
            #pragma unroll
            for (int i = 0; i < 6; ++i) {
                acc[i][0] = fmaf(a[i], b.x, acc[i][0]);
                acc[i][1] = fmaf(a[i], b.y, acc[i][1]);
                acc[i][2] = fmaf(a[i], b.z, acc[i][2]);
                acc[i][3] = fmaf(a[i], b.w, acc[i][3]);
            }
        }
    }

    // ---- write h tile (vectorized) ----
    float* hb = g_h + (size_t)head * Nv * CC;
    #pragma unroll
    for (int i = 0; i < 6; ++i) {
        int r = m0 + ty * 6 + i;
        if (r < Nv) {
            float4 v = make_float4(acc[i][0], acc[i][1], acc[i][2], acc[i][3]);
            *(float4*)(&hb[(size_t)r * CC + tx * 4]) = v;
        }
    }

    // ---- per-tile BN partials (deterministic, no atomics) ----
    __syncthreads();                       // done reading Bs; reuse as reduction buffer
    float* red = &Bs[0][0];                // layout: [2][16][64] = 2048 floats (fits in Bs)
    #pragma unroll
    for (int j = 0; j < 4; ++j) {
        float s = 0.f, q = 0.f;
        #pragma unroll
        for (int i = 0; i < 6; ++i) {
            int r = m0 + ty * 6 + i;
            float v = (r < Nv) ? acc[i][j] : 0.f;
            s += v; q += v * v;
        }
        red[0 * 1024 + ty * 64 + tx * 4 + j] = s;
        red[1 * 1024 + ty * 64 + tx * 4 + j] = q;
    }
    __syncthreads();
    if (tid < 2 * CC) {
        int w = tid >> 6;      // 0 = sum, 1 = sumsq
        int c = tid & 63;
        float s = 0.f;
        #pragma unroll
        for (int t = 0; t < 16; ++t) s += red[w * 1024 + t * 64 + c];
        g_part[(((size_t)head * ntiles + blockIdx.x) * 2 + w) * CC + c] = s;
    }
}

// ---------------------------------------------------------------------------
// Reduce per-tile partials -> fused BN scale/shift per (head, channel)
// ---------------------------------------------------------------------------
__global__ void reduce_stats(const float* __restrict__ gamma,
                             const float* __restrict__ beta,
                             int Nv, int ntiles)
{
    int t = blockIdx.x * blockDim.x + threadIdx.x;
    if (t >= NH * CC) return;
    int head = t / CC;
    int c    = t % CC;
    const float* p = g_part + (size_t)head * ntiles * 2 * CC;
    float s = 0.f, q = 0.f;
    for (int i = 0; i < ntiles; ++i) {
        s += p[(size_t)i * 2 * CC + c];
        q += p[(size_t)i * 2 * CC + CC + c];
    }
    float invN = 1.f / (float)Nv;
    float mean = s * invN;
    float var  = q * invN - mean * mean;
    float inv  = rsqrtf(var + BN_EPS);
    float sc   = inv * gamma[t];
    g_scale[t] = sc;
    g_shift[t] = beta[t] - mean * sc;
}

// ---------------------------------------------------------------------------
// Pass 2: one warp per (head, voxel). BN+ReLU then 1x1 conv (oc<=3) via
// warp-shuffle dot products. Output = flattened concat in head order.
// ---------------------------------------------------------------------------
__global__ __launch_bounds__(256) void pass2_kernel(
    const float* __restrict__ W1_0, const float* __restrict__ b1_0,
    const float* __restrict__ W1_1, const float* __restrict__ b1_1,
    const float* __restrict__ W1_2, const float* __restrict__ b1_2,
    const float* __restrict__ W1_3, const float* __restrict__ b1_3,
    const float* __restrict__ W1_4, const float* __restrict__ b1_4,
    float* __restrict__ out, int Nv)
{
    int wid  = (blockIdx.x * blockDim.x + threadIdx.x) >> 5;
    int lane = threadIdx.x & 31;
    if (wid >= NH * Nv) return;
    int head = wid / Nv;
    int n    = wid - head * Nv;

    size_t base = ((size_t)head * Nv + n) * CC;
    int c0 = lane, c1 = lane + 32;
    float h0 = g_h[base + c0];
    float h1 = g_h[base + c1];
    int s0 = head * CC + c0, s1 = head * CC + c1;
    float y0 = fmaxf(0.f, fmaf(h0, g_scale[s0], g_shift[s0]));
    float y1 = fmaxf(0.f, fmaf(h1, g_scale[s1], g_shift[s1]));

    const float* W1; const float* b1; int oc; int off;
    switch (head) {
        case 0:  W1 = W1_0; b1 = b1_0; oc = 3; off = 0; break;
        case 1:  W1 = W1_1; b1 = b1_1; oc = 2; off = 3; break;
        case 2:  W1 = W1_2; b1 = b1_2; oc = 1; off = 5; break;
        case 3:  W1 = W1_3; b1 = b1_3; oc = 3; off = 6; break;
        default: W1 = W1_4; b1 = b1_4; oc = 2; off = 9; break;
    }
    size_t ob = (size_t)off * Nv + (size_t)n * oc;
    for (int o = 0; o < oc; ++o) {
        float p = y0 * W1[c0 * oc + o] + y1 * W1[c1 * oc + o];
        #pragma unroll
        for (int s = 16; s > 0; s >>= 1)
            p += __shfl_down_sync(0xffffffffu, p, s);
        if (lane == 0) out[ob + o] = p + b1[o];
    }
}

// ---------------------------------------------------------------------------
extern "C" void kernel_launch(void* const* d_in, const int* in_sizes, int n_in,
                              void* d_out, int out_size)
{
    const float* feat  = (const float*)d_in[0];
    const int*   nbr   = (const int*)  d_in[1];
    const float* W3    = (const float*)d_in[2];
    const float* gamma = (const float*)d_in[3];
    const float* beta  = (const float*)d_in[4];

    int Nv = in_sizes[0] / CC;
    if (Nv > NMAX) Nv = NMAX;
    int ntiles = (Nv + TM - 1) / TM;

    dim3 g1(ntiles, NH);
    pass1_kernel<<<g1, 256>>>(feat, nbr, W3, Nv, ntiles);

    reduce_stats<<<1, NH * CC>>>(gamma, beta, Nv, ntiles);

    long long nthreads = (long long)NH * Nv * 32;
    int blocks2 = (int)((nthreads + 255) / 256);
    pass2_kernel<<<blocks2, 256>>>(
        (const float*)d_in[5],  (const float*)d_in[6],
        (const float*)d_in[7],  (const float*)d_in[8],
        (const float*)d_in[9],  (const float*)d_in[10],
        (const float*)d_in[11], (const float*)d_in[12],
        (const float*)d_in[13], (const float*)d_in[14],
        (float*)d_out, Nv);
}

// round 2
// speedup vs baseline: 1.1477x; 1.1477x over previous
#include <cuda_runtime.h>

#define CC     64
#define KK9    9
#define NH     5
#define NMAX   150000
#define TM     96
#define MAXTILES ((NMAX + TM - 1) / TM)   // 1563
#define BN_EPS 1e-5f

// Scratch (device globals -- no allocations allowed)
__device__ float g_h[(size_t)NH * NMAX * CC];                 // 192 MB intermediate
__device__ float g_part[(size_t)NH * MAXTILES * 2 * CC];      // per-tile sum/sumsq partials
__device__ float g_scale[NH * CC];
__device__ float g_shift[NH * CC];

// ---------------------------------------------------------------------------
// Pass 1: gather-GEMM  h[head, n, o] = sum_k sum_c feat[nbr[n,k], c] * W3[head,k,c,o]
// Tile: 96 voxels x 64 out-channels, K loop = 9 slabs of 64, inner K unrolled x4
// with float4 LDS on both operands (cuts L1 wavefronts ~3x vs scalar-A version).
// 256 threads, each computes 6 rows x 4 cols. Also emits per-tile BN partials.
// ---------------------------------------------------------------------------
__global__ __launch_bounds__(256, 3) void pass1_kernel(
    const float* __restrict__ feat,
    const int*   __restrict__ nbr,
    const float* __restrict__ W3,
    int Nv, int ntiles)
{
    __shared__ float As[TM][CC + 4];   // gathered tile, pad 4 -> row stride 272B (16B aligned)
    __shared__ float Bs[CC][CC];       // W3[head][k] slab (reused as reduction buffer after GEMM)

    const int tid  = threadIdx.x;
    const int tx   = tid & 15;         // 16 col-groups of 4
    const int ty   = tid >> 4;         // 16 row-groups of 6
    const int m0   = blockIdx.x * TM;
    const int head = blockIdx.y;

    float acc[6][4];
    #pragma unroll
    for (int i = 0; i < 6; ++i)
        #pragma unroll
        for (int j = 0; j < 4; ++j) acc[i][j] = 0.f;

    const float* Wh = W3 + (size_t)head * KK9 * CC * CC;

    for (int k = 0; k < KK9; ++k) {
        __syncthreads();   // protect smem from previous iteration's readers

        // B slab: 4096 floats, coalesced float4
        {
            const float4* bsrc = (const float4*)(Wh + (size_t)k * CC * CC);
            float4* bdst = (float4*)(&Bs[0][0]);
            #pragma unroll
            for (int w = 0; w < 4; ++w)
                bdst[tid + w * 256] = bsrc[tid + w * 256];
        }
        // A tile: gather rows (index computed inline; 96 rows x 16 float4)
        #pragma unroll
        for (int w = 0; w < 6; ++w) {
            int i   = tid + w * 256;         // 1536 = 6*256 exactly
            int row = i >> 4;
            int c4  = i & 15;
            int m   = m0 + row;
            int idx = (m < Nv) ? nbr[(size_t)m * KK9 + k] : -1;
            float4 v = make_float4(0.f, 0.f, 0.f, 0.f);
            if (idx >= 0)
                v = ((const float4*)(feat + (size_t)idx * CC))[c4];
            *(float4*)(&As[row][c4 * 4]) = v;
        }
        __syncthreads();

        // 96x64x64 GEMM slab, K unrolled by 4 with float4 smem loads
        #pragma unroll
        for (int kq = 0; kq < CC / 4; ++kq) {
            float4 b0 = *(const float4*)(&Bs[kq * 4 + 0][tx * 4]);
            float4 b1 = *(const float4*)(&Bs[kq * 4 + 1][tx * 4]);
            float4 b2 = *(const float4*)(&Bs[kq * 4 + 2][tx * 4]);
            float4 b3 = *(const float4*)(&Bs[kq * 4 + 3][tx * 4]);
            #pragma unroll
            for (int i = 0; i < 6; ++i) {
                float4 a = *(const float4*)(&As[ty * 6 + i][kq * 4]);
                acc[i][0] = fmaf(a.x, b0.x, acc[i][0]);
                acc[i][1] = fmaf(a.x, b0.y, acc[i][1]);
                acc[i][2] = fmaf(a.x, b0.z, acc[i][2]);
                acc[i][3] = fmaf(a.x, b0.w, acc[i][3]);
                acc[i][0] = fmaf(a.y, b1.x, acc[i][0]);
                acc[i][1] = fmaf(a.y, b1.y, acc[i][1]);
                acc[i][2] = fmaf(a.y, b1.z, acc[i][2]);
                acc[i][3] = fmaf(a.y, b1.w, acc[i][3]);
                acc[i][0] = fmaf(a.z, b2.x, acc[i][0]);
                acc[i][1] = fmaf(a.z, b2.y, acc[i][1]);
                acc[i][2] = fmaf(a.z, b2.z, acc[i][2]);
                acc[i][3] = fmaf(a.z, b2.w, acc[i][3]);
                acc[i][0] = fmaf(a.w, b3.x, acc[i][0]);
                acc[i][1] = fmaf(a.w, b3.y, acc[i][1]);
                acc[i][2] = fmaf(a.w, b3.z, acc[i][2]);
                acc[i][3] = fmaf(a.w, b3.w, acc[i][3]);
            }
        }
    }

    // ---- write h tile (vectorized) ----
    float* hb = g_h + (size_t)head * Nv * CC;
    #pragma unroll
    for (int i = 0; i < 6; ++i) {
        int r = m0 + ty * 6 + i;
        if (r < Nv) {
            float4 v = make_float4(acc[i][0], acc[i][1], acc[i][2], acc[i][3]);
            *(float4*)(&hb[(size_t)r * CC + tx * 4]) = v;
        }
    }

    // ---- per-tile BN partials (deterministic, no atomics) ----
    __syncthreads();                       // done reading Bs; reuse as reduction buffer
    float* red = &Bs[0][0];                // layout: [2][16][64] = 2048 floats (fits in Bs)
    #pragma unroll
    for (int j = 0; j < 4; ++j) {
        float s = 0.f, q = 0.f;
        #pragma unroll
        for (int i = 0; i < 6; ++i) {
            int r = m0 + ty * 6 + i;
            float v = (r < Nv) ? acc[i][j] : 0.f;
            s += v; q += v * v;
        }
        red[0 * 1024 + ty * 64 + tx * 4 + j] = s;
        red[1 * 1024 + ty * 64 + tx * 4 + j] = q;
    }
    __syncthreads();
    if (tid < 2 * CC) {
        int w = tid >> 6;      // 0 = sum, 1 = sumsq
        int c = tid & 63;
        float s = 0.f;
        #pragma unroll
        for (int t = 0; t < 16; ++t) s += red[w * 1024 + t * 64 + c];
        g_part[(((size_t)head * ntiles + blockIdx.x) * 2 + w) * CC + c] = s;
    }
}

// ---------------------------------------------------------------------------
// Reduce per-tile partials -> fused BN scale/shift. One warp per (head, chan).
// ---------------------------------------------------------------------------
__global__ __launch_bounds__(256) void reduce_stats(
    const float* __restrict__ gamma,
    const float* __restrict__ beta,
    int Nv, int ntiles)
{
    int gw   = (blockIdx.x * blockDim.x + threadIdx.x) >> 5;
    int lane = threadIdx.x & 31;
    if (gw >= NH * CC) return;
    int head = gw / CC;
    int c    = gw % CC;
    const float* p = g_part + (size_t)head * ntiles * 2 * CC;
    float s = 0.f, q = 0.f;
    for (int i = lane; i < ntiles; i += 32) {
        s += p[(size_t)i * 2 * CC + c];
        q += p[(size_t)i * 2 * CC + CC + c];
    }
    #pragma unroll
    for (int sh = 16; sh > 0; sh >>= 1) {
        s += __shfl_down_sync(0xffffffffu, s, sh);
        q += __shfl_down_sync(0xffffffffu, q, sh);
    }
    if (lane == 0) {
        float invN = 1.f / (float)Nv;
        float mean = s * invN;
        float var  = q * invN - mean * mean;
        float inv  = rsqrtf(var + BN_EPS);
        float sc   = inv * gamma[gw];
        g_scale[gw] = sc;
        g_shift[gw] = beta[gw] - mean * sc;
    }
}

// ---------------------------------------------------------------------------
// Pass 2: one warp per (head, voxel). BN+ReLU then 1x1 conv (oc<=3) via
// warp-shuffle dot products. Output = flattened concat in head order.
// ---------------------------------------------------------------------------
__global__ __launch_bounds__(256) void pass2_kernel(
    const float* __restrict__ W1_0, const float* __restrict__ b1_0,
    const float* __restrict__ W1_1, const float* __restrict__ b1_1,
    const float* __restrict__ W1_2, const float* __restrict__ b1_2,
    const float* __restrict__ W1_3, const float* __restrict__ b1_3,
    const float* __restrict__ W1_4, const float* __restrict__ b1_4,
    float* __restrict__ out, int Nv)
{
    int wid  = (blockIdx.x * blockDim.x + threadIdx.x) >> 5;
    int lane = threadIdx.x & 31;
    if (wid >= NH * Nv) return;
    int head = wid / Nv;
    int n    = wid - head * Nv;

    size_t base = ((size_t)head * Nv + n) * CC;
    int c0 = lane, c1 = lane + 32;
    float h0 = g_h[base + c0];
    float h1 = g_h[base + c1];
    int s0 = head * CC + c0, s1 = head * CC + c1;
    float y0 = fmaxf(0.f, fmaf(h0, g_scale[s0], g_shift[s0]));
    float y1 = fmaxf(0.f, fmaf(h1, g_scale[s1], g_shift[s1]));

    const float* W1; const float* b1; int oc; int off;
    switch (head) {
        case 0:  W1 = W1_0; b1 = b1_0; oc = 3; off = 0; break;
        case 1:  W1 = W1_1; b1 = b1_1; oc = 2; off = 3; break;
        case 2:  W1 = W1_2; b1 = b1_2; oc = 1; off = 5; break;
        case 3:  W1 = W1_3; b1 = b1_3; oc = 3; off = 6; break;
        default: W1 = W1_4; b1 = b1_4; oc = 2; off = 9; break;
    }
    size_t ob = (size_t)off * Nv + (size_t)n * oc;
    for (int o = 0; o < oc; ++o) {
        float p = y0 * W1[c0 * oc + o] + y1 * W1[c1 * oc + o];
        #pragma unroll
        for (int s = 16; s > 0; s >>= 1)
            p += __shfl_down_sync(0xffffffffu, p, s);
        if (lane == 0) out[ob + o] = p + b1[o];
    }
}

// ---------------------------------------------------------------------------
extern "C" void kernel_launch(void* const* d_in, const int* in_sizes, int n_in,
                              void* d_out, int out_size)
{
    const float* feat  = (const float*)d_in[0];
    const int*   nbr   = (const int*)  d_in[1];
    const float* W3    = (const float*)d_in[2];
    const float* gamma = (const float*)d_in[3];
    const float* beta  = (const float*)d_in[4];

    int Nv = in_sizes[0] / CC;
    if (Nv > NMAX) Nv = NMAX;
    int ntiles = (Nv + TM - 1) / TM;

    dim3 g1(ntiles, NH);
    pass1_kernel<<<g1, 256>>>(feat, nbr, W3, Nv, ntiles);

    int warps = NH * CC;
    reduce_stats<<<(warps * 32 + 255) / 256, 256>>>(gamma, beta, Nv, ntiles);

    long long nthreads = (long long)NH * Nv * 32;
    int blocks2 = (int)((nthreads + 255) / 256);
    pass2_kernel<<<blocks2, 256>>>(
        (const float*)d_in[5],  (const float*)d_in[6],
        (const float*)d_in[7],  (const float*)d_in[8],
        (const float*)d_in[9],  (const float*)d_in[10],
        (const float*)d_in[11], (const float*)d_in[12],
        (const float*)d_in[13], (const float*)d_in[14],
        (float*)d_out, Nv);
}

// round 4
// speedup vs baseline: 2.5270x; 2.2018x over previous
#include <cuda_runtime.h>
#include <cuda_bf16.h>
#include <cstdint>

#define CC     64
#define KK9    9
#define NH     5
#define NMAX   150000
#define TMM    128
#define MAXT   ((NMAX + TMM - 1) / TMM)     // 1172
#define BN_EPS 1e-5f

// ---------------- device global scratch (no allocations allowed) ----------------
__device__ __nv_bfloat16 g_fhi[(size_t)NMAX * CC];
__device__ __nv_bfloat16 g_flo[(size_t)NMAX * CC];
__device__ __nv_bfloat16 g_Bbf[(size_t)NH * KK9 * 2 * 4096];  // pre-swizzled [n][k] slabs
__device__ float g_h[(size_t)NH * NMAX * CC];                 // 192 MB intermediate
__device__ float g_part[(size_t)NH * MAXT * 2 * CC];
__device__ float g_scale[NH * CC];
__device__ float g_shift[NH * CC];

// ---------------- helpers ----------------
__device__ __forceinline__ uint32_t smem_u32(const void* p) {
    uint32_t a;
    asm("{ .reg .u64 t; cvta.to.shared.u64 t, %1; cvt.u32.u64 %0, t; }" : "=r"(a) : "l"(p));
    return a;
}
__device__ __forceinline__ void cpa16(uint32_t dst, const void* src, uint32_t sz) {
    asm volatile("cp.async.cg.shared.global [%0], [%1], 16, %2;"
                 :: "r"(dst), "l"(src), "r"(sz) : "memory");
}
__device__ __forceinline__ void cpa_commit() {
    asm volatile("cp.async.commit_group;" ::: "memory");
}
__device__ __forceinline__ void ldx4(uint32_t* r, uint32_t addr) {
    asm volatile("ldmatrix.sync.aligned.m8n8.x4.shared.b16 {%0,%1,%2,%3}, [%4];"
                 : "=r"(r[0]), "=r"(r[1]), "=r"(r[2]), "=r"(r[3]) : "r"(addr));
}
__device__ __forceinline__ void mma_bf16(float* c, const uint32_t* a, const uint32_t* b) {
    asm volatile(
        "mma.sync.aligned.m16n8k16.row.col.f32.bf16.bf16.f32 "
        "{%0,%1,%2,%3}, {%4,%5,%6,%7}, {%8,%9}, {%0,%1,%2,%3};"
        : "+f"(c[0]), "+f"(c[1]), "+f"(c[2]), "+f"(c[3])
        : "r"(a[0]), "r"(a[1]), "r"(a[2]), "r"(a[3]), "r"(b[0]), "r"(b[1]));
}

// ---------------- prep kernels ----------------
__global__ __launch_bounds__(256) void split_feat(const float* __restrict__ f, int n) {
    int i = blockIdx.x * blockDim.x + threadIdx.x;
    if (i >= n) return;
    float x = f[i];
    __nv_bfloat16 hi = __float2bfloat16(x);
    g_fhi[i] = hi;
    g_flo[i] = __float2bfloat16(x - __bfloat162float(hi));
}

// W3 [h][k][c][o] -> slabs [h*9+k][hi|lo][n=o][k=c] bf16, 16B-xor swizzled for ldmatrix
__global__ __launch_bounds__(256) void split_w3(const float* __restrict__ w) {
    int i = blockIdx.x * blockDim.x + threadIdx.x;
    if (i >= NH * KK9 * 4096) return;
    int slab = i >> 12;
    int r = i & 4095;
    int c = r >> 6;        // K index
    int o = r & 63;        // N index
    float x = w[i];
    __nv_bfloat16 hi = __float2bfloat16(x);
    __nv_bfloat16 lo = __float2bfloat16(x - __bfloat162float(hi));
    // element pos inside 8KB (4096-elem) half-slab: row o (64 bf16), swizzled 16B units
    int e = (o * 8 + ((c >> 3) ^ (o & 7))) * 8 + (c & 7);
    g_Bbf[(size_t)slab * 8192 + e]        = hi;
    g_Bbf[(size_t)slab * 8192 + 4096 + e] = lo;
}

// ---------------- pass1: bf16-split mma.sync gather-GEMM ----------------
// SMEM: A: 2 stages x (hi 16KB + lo 16KB) = 64KB at 0
//       B: 2 stages x (hi 8KB  + lo 8KB)  = 32KB at 65536
//       red: 4 x 2 x 64 floats = 2KB at 98304
#define SM_A    0u
#define SM_B    65536u
#define SM_RED  98304u
#define SM_TOT  (SM_RED + 2048u)

__device__ __forceinline__ void gatherA(uint32_t sb, int stage,
                                        const int* __restrict__ nbr,
                                        int m0, int Nv, int k)
{
    const int t   = threadIdx.x;
    const int row = t >> 1;          // 128 rows, 2 threads each
    const int m   = m0 + row;
    int idx = -1;
    if (m < Nv) idx = __ldg(&nbr[(size_t)m * KK9 + k]);
    uint32_t sz = (idx >= 0) ? 16u : 0u;
    int ic = (idx >= 0) ? idx : 0;
    const char* srcH = (const char*)g_fhi + (size_t)ic * 128 + (t & 1) * 64;
    const char* srcL = (const char*)g_flo + (size_t)ic * 128 + (t & 1) * 64;
    uint32_t dbase = sb + SM_A + (uint32_t)stage * 32768u + (uint32_t)row * 128u;
    #pragma unroll
    for (int j = 0; j < 4; ++j) {
        int c16 = (t & 1) * 4 + j;
        uint32_t off = (uint32_t)((c16 ^ (row & 7)) << 4);
        cpa16(dbase + off,            srcH + j * 16, sz);
        cpa16(dbase + 16384u + off,   srcL + j * 16, sz);
    }
}

__device__ __forceinline__ void copyB(uint32_t sb, int stage, int slab) {
    const int t = threadIdx.x;
    const char* src = (const char*)g_Bbf + (size_t)slab * 16384;
    uint32_t dst = sb + SM_B + (uint32_t)stage * 16384u;
    #pragma unroll
    for (int j = 0; j < 4; ++j) {
        int i = t + j * 256;
        cpa16(dst + (uint32_t)i * 16u, src + (size_t)i * 16, 16u);
    }
}

__global__ __launch_bounds__(256, 2) void pass1_mma(
    const int* __restrict__ nbr, int Nv, int ntiles)
{
    extern __shared__ char smem[];
    const uint32_t sb = smem_u32(smem);
    const int tid  = threadIdx.x;
    const int wid  = tid >> 5;
    const int lane = tid & 31;
    const int m0   = blockIdx.x * TMM;
    const int head = blockIdx.y;

    const int wm = wid & 3;            // 4 M-warps (32 rows each)
    const int wn = wid >> 2;           // 2 N-warps (32 cols each)
    const int warpM0 = wm * 32;
    const int warpN0 = wn * 32;

    float acc[2][4][4];                // [mf][nf][4]
    #pragma unroll
    for (int i = 0; i < 2; ++i)
        #pragma unroll
        for (int j = 0; j < 4; ++j)
            #pragma unroll
            for (int q = 0; q < 4; ++q) acc[i][j][q] = 0.f;

    // prologue
    gatherA(sb, 0, nbr, m0, Nv, 0);
    copyB(sb, 0, head * KK9 + 0);
    cpa_commit();

    for (int k = 0; k < KK9; ++k) {
        const int stage = k & 1;
        if (k + 1 < KK9) {
            gatherA(sb, stage ^ 1, nbr, m0, Nv, k + 1);
            copyB(sb, stage ^ 1, head * KK9 + k + 1);
            cpa_commit();
            asm volatile("cp.async.wait_group 1;" ::: "memory");
        } else {
            asm volatile("cp.async.wait_group 0;" ::: "memory");
        }
        __syncthreads();

        const uint32_t Ah = sb + SM_A + (uint32_t)stage * 32768u;
        const uint32_t Al = Ah + 16384u;
        const uint32_t Bh = sb + SM_B + (uint32_t)stage * 16384u;
        const uint32_t Bl = Bh + 8192u;

        #pragma unroll
        for (int kk = 0; kk < 4; ++kk) {
            uint32_t ah[2][4], al[2][4];
            #pragma unroll
            for (int mf = 0; mf < 2; ++mf) {
                int rr = warpM0 + mf * 16 + (lane & 7) + ((lane >> 3) & 1) * 8;
                int c16 = kk * 2 + (lane >> 4);
                uint32_t byte = (uint32_t)(rr * 128 + ((c16 ^ (rr & 7)) << 4));
                ldx4(ah[mf], Ah + byte);
                ldx4(al[mf], Al + byte);
            }
            uint32_t bh[2][4], bl[2][4];   // [pair p: nf {2p,2p+1}]
            #pragma unroll
            for (int p = 0; p < 2; ++p) {
                int nn = warpN0 + p * 16 + (lane & 7) + ((lane >> 4) << 3);
                int c16 = kk * 2 + ((lane >> 3) & 1);
                uint32_t byte = (uint32_t)(nn * 128 + ((c16 ^ (nn & 7)) << 4));
                ldx4(bh[p], Bh + byte);
                ldx4(bl[p], Bl + byte);
            }
            #pragma unroll
            for (int mf = 0; mf < 2; ++mf)
                #pragma unroll
                for (int nf = 0; nf < 4; ++nf) {
                    const uint32_t* bq = &bh[nf >> 1][(nf & 1) * 2];
                    const uint32_t* bw = &bl[nf >> 1][(nf & 1) * 2];
                    mma_bf16(acc[mf][nf], ah[mf], bq);   // hi*hi
                    mma_bf16(acc[mf][nf], ah[mf], bw);   // hi*lo
                    mma_bf16(acc[mf][nf], al[mf], bq);   // lo*hi
                }
        }
        __syncthreads();
    }

    // ---- epilogue: write g_h + BN partials ----
    float* hb = g_h + (size_t)head * Nv * CC;
    #pragma unroll
    for (int mf = 0; mf < 2; ++mf)
        #pragma unroll
        for (int nf = 0; nf < 4; ++nf) {
            int r = m0 + warpM0 + mf * 16 + (lane >> 2);
            int c = warpN0 + nf * 8 + (lane & 3) * 2;
            float* a = acc[mf][nf];
            if (r < Nv)     *(float2*)(hb + (size_t)r * CC + c)       = make_float2(a[0], a[1]);
            if (r + 8 < Nv) *(float2*)(hb + (size_t)(r + 8) * CC + c) = make_float2(a[2], a[3]);
        }

    float* red = (float*)(smem + SM_RED);   // [4 wm][2 stat][64 col]
    #pragma unroll
    for (int nf = 0; nf < 4; ++nf) {
        float s0 = 0.f, s1 = 0.f, q0 = 0.f, q1 = 0.f;
        #pragma unroll
        for (int mf = 0; mf < 2; ++mf) {
            float* a = acc[mf][nf];
            s0 += a[0] + a[2];  q0 += a[0] * a[0] + a[2] * a[2];
            s1 += a[1] + a[3];  q1 += a[1] * a[1] + a[3] * a[3];
        }
        #pragma unroll
        for (int sh = 4; sh < 32; sh <<= 1) {
            s0 += __shfl_xor_sync(0xffffffffu, s0, sh);
            s1 += __shfl_xor_sync(0xffffffffu, s1, sh);
            q0 += __shfl_xor_sync(0xffffffffu, q0, sh);
            q1 += __shfl_xor_sync(0xffffffffu, q1, sh);
        }
        if (lane < 4) {
            int c = warpN0 + nf * 8 + lane * 2;
            red[(wm * 2 + 0) * 64 + c]     = s0;
            red[(wm * 2 + 0) * 64 + c + 1] = s1;
            red[(wm * 2 + 1) * 64 + c]     = q0;
            red[(wm * 2 + 1) * 64 + c + 1] = q1;
        }
    }
    __syncthreads();
    if (tid < 128) {
        int w = tid >> 6, col = tid & 63;
        float v = red[(0 * 2 + w) * 64 + col] + red[(1 * 2 + w) * 64 + col]
                + red[(2 * 2 + w) * 64 + col] + red[(3 * 2 + w) * 64 + col];
        g_part[(((size_t)head * ntiles + blockIdx.x) * 2 + w) * CC + col] = v;
    }
}

// ---------------- BN stats reduce ----------------
__global__ __launch_bounds__(256) void reduce_stats(
    const float* __restrict__ gamma, const float* __restrict__ beta,
    int Nv, int ntiles)
{
    int gw   = (blockIdx.x * blockDim.x + threadIdx.x) >> 5;
    int lane = threadIdx.x & 31;
    if (gw >= NH * CC) return;
    int head = gw / CC, c = gw % CC;
    const float* p = g_part + (size_t)head * ntiles * 2 * CC;
    float s = 0.f, q = 0.f;
    for (int i = lane; i < ntiles; i += 32) {
        s += p[(size_t)i * 2 * CC + c];
        q += p[(size_t)i * 2 * CC + CC + c];
    }
    #pragma unroll
    for (int sh = 16; sh > 0; sh >>= 1) {
        s += __shfl_down_sync(0xffffffffu, s, sh);
        q += __shfl_down_sync(0xffffffffu, q, sh);
    }
    if (lane == 0) {
        float invN = 1.f / (float)Nv;
        float mean = s * invN;
        float var  = q * invN - mean * mean;
        float inv  = rsqrtf(var + BN_EPS);
        float sc   = inv * gamma[gw];
        g_scale[gw] = sc;
        g_shift[gw] = beta[gw] - mean * sc;
    }
}

// ---------------- pass 2: BN + ReLU + 1x1 convs ----------------
__global__ __launch_bounds__(256) void pass2_kernel(
    const float* __restrict__ W1_0, const float* __restrict__ b1_0,
    const float* __restrict__ W1_1, const float* __restrict__ b1_1,
    const float* __restrict__ W1_2, const float* __restrict__ b1_2,
    const float* __restrict__ W1_3, const float* __restrict__ b1_3,
    const float* __restrict__ W1_4, const float* __restrict__ b1_4,
    float* __restrict__ out, int Nv)
{
    int wid  = (blockIdx.x * blockDim.x + threadIdx.x) >> 5;
    int lane = threadIdx.x & 31;
    if (wid >= NH * Nv) return;
    int head = wid / Nv;
    int n    = wid - head * Nv;

    size_t base = ((size_t)head * Nv + n) * CC;
    int c0 = lane, c1 = lane + 32;
    float h0 = g_h[base + c0];
    float h1 = g_h[base + c1];
    int s0 = head * CC + c0, s1 = head * CC + c1;
    float y0 = fmaxf(0.f, fmaf(h0, g_scale[s0], g_shift[s0]));
    float y1 = fmaxf(0.f, fmaf(h1, g_scale[s1], g_shift[s1]));

    const float* W1; const float* b1; int oc; int off;
    switch (head) {
        case 0:  W1 = W1_0; b1 = b1_0; oc = 3; off = 0; break;
        case 1:  W1 = W1_1; b1 = b1_1; oc = 2; off = 3; break;
        case 2:  W1 = W1_2; b1 = b1_2; oc = 1; off = 5; break;
        case 3:  W1 = W1_3; b1 = b1_3; oc = 3; off = 6; break;
        default: W1 = W1_4; b1 = b1_4; oc = 2; off = 9; break;
    }
    size_t ob = (size_t)off * Nv + (size_t)n * oc;
    for (int o = 0; o < oc; ++o) {
        float p = y0 * W1[c0 * oc + o] + y1 * W1[c1 * oc + o];
        #pragma unroll
        for (int s = 16; s > 0; s >>= 1)
            p += __shfl_down_sync(0xffffffffu, p, s);
        if (lane == 0) out[ob + o] = p + b1[o];
    }
}

// ---------------------------------------------------------------------------
extern "C" void kernel_launch(void* const* d_in, const int* in_sizes, int n_in,
                              void* d_out, int out_size)
{
    const float* feat  = (const float*)d_in[0];
    const int*   nbr   = (const int*)  d_in[1];
    const float* W3    = (const float*)d_in[2];
    const float* gamma = (const float*)d_in[3];
    const float* beta  = (const float*)d_in[4];

    int Nv = in_sizes[0] / CC;
    if (Nv > NMAX) Nv = NMAX;
    int ntiles = (Nv + TMM - 1) / TMM;

    static int smem_set = 0;
    if (!smem_set) {
        cudaFuncSetAttribute(pass1_mma, cudaFuncAttributeMaxDynamicSharedMemorySize, SM_TOT);
        smem_set = 1;
    }

    int nf = Nv * CC;
    split_feat<<<(nf + 255) / 256, 256>>>(feat, nf);
    split_w3<<<(NH * KK9 * 4096 + 255) / 256, 256>>>(W3);

    dim3 g1(ntiles, NH);
    pass1_mma<<<g1, 256, SM_TOT>>>(nbr, Nv, ntiles);

    reduce_stats<<<(NH * CC * 32 + 255) / 256, 256>>>(gamma, beta, Nv, ntiles);

    long long nthreads = (long long)NH * Nv * 32;
    int blocks2 = (int)((nthreads + 255) / 256);
    pass2_kernel<<<blocks2, 256>>>(
        (const float*)d_in[5],  (const float*)d_in[6],
        (const float*)d_in[7],  (const float*)d_in[8],
        (const float*)d_in[9],  (const float*)d_in[10],
        (const float*)d_in[11], (const float*)d_in[12],
        (const float*)d_in[13], (const float*)d_in[14],
        (float*)d_out, Nv);
}

// round 5
// speedup vs baseline: 3.3148x; 1.3117x over previous
#include <cuda_runtime.h>
#include <cuda_fp16.h>
#include <cstdint>

#define CC     64
#define KK9    9
#define NH     5
#define NMAX   150000
#define TMM    128
#define MAXT   ((NMAX + TMM - 1) / TMM)     // 1172
#define BN_EPS 1e-5f

// ---------------- device global scratch (no allocations allowed) ----------------
__device__ __half g_f16[(size_t)NMAX * CC];                    // features hi (fp16)
__device__ __half g_B16[(size_t)NH * KK9 * 2 * 4096];          // weights hi|lo, swizzled
__device__ float g_h[(size_t)NH * NMAX * CC];                  // 192 MB intermediate
__device__ float g_part[(size_t)NH * 2 * CC * MAXT];           // [head][stat][chan][tile]
__device__ float g_scale[NH * CC];
__device__ float g_shift[NH * CC];

// ---------------- helpers ----------------
__device__ __forceinline__ uint32_t smem_u32(const void* p) {
    uint32_t a;
    asm("{ .reg .u64 t; cvta.to.shared.u64 t, %1; cvt.u32.u64 %0, t; }" : "=r"(a) : "l"(p));
    return a;
}
__device__ __forceinline__ void cpa16(uint32_t dst, const void* src, uint32_t sz) {
    asm volatile("cp.async.cg.shared.global [%0], [%1], 16, %2;"
                 :: "r"(dst), "l"(src), "r"(sz) : "memory");
}
__device__ __forceinline__ void cpa_commit() {
    asm volatile("cp.async.commit_group;" ::: "memory");
}
__device__ __forceinline__ void ldx4(uint32_t* r, uint32_t addr) {
    asm volatile("ldmatrix.sync.aligned.m8n8.x4.shared.b16 {%0,%1,%2,%3}, [%4];"
                 : "=r"(r[0]), "=r"(r[1]), "=r"(r[2]), "=r"(r[3]) : "r"(addr));
}
__device__ __forceinline__ void mma_f16(float* c, const uint32_t* a, const uint32_t* b) {
    asm volatile(
        "mma.sync.aligned.m16n8k16.row.col.f32.f16.f16.f32 "
        "{%0,%1,%2,%3}, {%4,%5,%6,%7}, {%8,%9}, {%0,%1,%2,%3};"
        : "+f"(c[0]), "+f"(c[1]), "+f"(c[2]), "+f"(c[3])
        : "r"(a[0]), "r"(a[1]), "r"(a[2]), "r"(a[3]), "r"(b[0]), "r"(b[1]));
}

// ---------------- prep kernels ----------------
__global__ __launch_bounds__(256) void prep_feat(const float* __restrict__ f, int n) {
    int i = blockIdx.x * blockDim.x + threadIdx.x;
    if (i >= n) return;
    g_f16[i] = __float2half(f[i]);
}

// W3 [h][k][c][o] -> slabs [h*9+k][hi|lo][n=o][k=c] fp16, 16B-xor swizzled for ldmatrix
__global__ __launch_bounds__(256) void prep_w3(const float* __restrict__ w) {
    int i = blockIdx.x * blockDim.x + threadIdx.x;
    if (i >= NH * KK9 * 4096) return;
    int slab = i >> 12;
    int r = i & 4095;
    int c = r >> 6;        // K index
    int o = r & 63;        // N index
    float x = w[i];
    __half hi = __float2half(x);
    __half lo = __float2half(x - __half2float(hi));
    int e = (o * 8 + ((c >> 3) ^ (o & 7))) * 8 + (c & 7);
    g_B16[(size_t)slab * 8192 + e]        = hi;
    g_B16[(size_t)slab * 8192 + 4096 + e] = lo;
}

// ---------------- pass1: fp16 2-term mma.sync gather-GEMM ----------------
// SMEM: A: 2 stages x 16KB = 32KB at 0
//       B: 2 stages x (hi 8KB + lo 8KB) = 32KB at 32768
//       red: 4 x 2 x 64 floats = 2KB at 65536
#define SM_A    0u
#define SM_B    32768u
#define SM_RED  65536u
#define SM_TOT  (SM_RED + 2048u)

__device__ __forceinline__ void gatherA(uint32_t sb, int stage,
                                        const int* __restrict__ nbr,
                                        int m0, int Nv, int k)
{
    const int t   = threadIdx.x;
    const int row = t >> 1;          // 128 rows, 2 threads each
    const int m   = m0 + row;
    int idx = -1;
    if (m < Nv) idx = __ldg(&nbr[(size_t)m * KK9 + k]);
    uint32_t sz = (idx >= 0) ? 16u : 0u;
    int ic = (idx >= 0) ? idx : 0;
    const char* src = (const char*)g_f16 + (size_t)ic * 128 + (t & 1) * 64;
    uint32_t dbase = sb + SM_A + (uint32_t)stage * 16384u + (uint32_t)row * 128u;
    #pragma unroll
    for (int j = 0; j < 4; ++j) {
        int c16 = (t & 1) * 4 + j;
        uint32_t off = (uint32_t)((c16 ^ (row & 7)) << 4);
        cpa16(dbase + off, src + j * 16, sz);
    }
}

__device__ __forceinline__ void copyB(uint32_t sb, int stage, int slab) {
    const int t = threadIdx.x;
    const char* src = (const char*)g_B16 + (size_t)slab * 16384;
    uint32_t dst = sb + SM_B + (uint32_t)stage * 16384u;
    #pragma unroll
    for (int j = 0; j < 4; ++j) {
        int i = t + j * 256;
        cpa16(dst + (uint32_t)i * 16u, src + (size_t)i * 16, 16u);
    }
}

__global__ __launch_bounds__(256, 3) void pass1_mma(
    const int* __restrict__ nbr, int Nv, int ntiles)
{
    extern __shared__ char smem[];
    const uint32_t sb = smem_u32(smem);
    const int tid  = threadIdx.x;
    const int wid  = tid >> 5;
    const int lane = tid & 31;
    const int m0   = blockIdx.x * TMM;
    const int head = blockIdx.y;

    const int wm = wid & 3;            // 4 M-warps (32 rows each)
    const int wn = wid >> 2;           // 2 N-warps (32 cols each)
    const int warpM0 = wm * 32;
    const int warpN0 = wn * 32;

    float acc[2][4][4];                // [mf][nf][4]
    #pragma unroll
    for (int i = 0; i < 2; ++i)
        #pragma unroll
        for (int j = 0; j < 4; ++j)
            #pragma unroll
            for (int q = 0; q < 4; ++q) acc[i][j][q] = 0.f;

    // prologue
    gatherA(sb, 0, nbr, m0, Nv, 0);
    copyB(sb, 0, head * KK9 + 0);
    cpa_commit();

    for (int k = 0; k < KK9; ++k) {
        const int stage = k & 1;
        if (k + 1 < KK9) {
            gatherA(sb, stage ^ 1, nbr, m0, Nv, k + 1);
            copyB(sb, stage ^ 1, head * KK9 + k + 1);
            cpa_commit();
            asm volatile("cp.async.wait_group 1;" ::: "memory");
        } else {
            asm volatile("cp.async.wait_group 0;" ::: "memory");
        }
        __syncthreads();

        const uint32_t Ah = sb + SM_A + (uint32_t)stage * 16384u;
        const uint32_t Bh = sb + SM_B + (uint32_t)stage * 16384u;
        const uint32_t Bl = Bh + 8192u;

        #pragma unroll
        for (int kk = 0; kk < 4; ++kk) {
            uint32_t ah[2][4];
            #pragma unroll
            for (int mf = 0; mf < 2; ++mf) {
                int rr = warpM0 + mf * 16 + (lane & 7) + ((lane >> 3) & 1) * 8;
                int c16 = kk * 2 + (lane >> 4);
                uint32_t byte = (uint32_t)(rr * 128 + ((c16 ^ (rr & 7)) << 4));
                ldx4(ah[mf], Ah + byte);
            }
            uint32_t bh[2][4], bl[2][4];   // [pair p: nf {2p,2p+1}]
            #pragma unroll
            for (int p = 0; p < 2; ++p) {
                int nn = warpN0 + p * 16 + (lane & 7) + ((lane >> 4) << 3);
                int c16 = kk * 2 + ((lane >> 3) & 1);
                uint32_t byte = (uint32_t)(nn * 128 + ((c16 ^ (nn & 7)) << 4));
                ldx4(bh[p], Bh + byte);
                ldx4(bl[p], Bl + byte);
            }
            #pragma unroll
            for (int mf = 0; mf < 2; ++mf)
                #pragma unroll
                for (int nf = 0; nf < 4; ++nf) {
                    const uint32_t* bq = &bh[nf >> 1][(nf & 1) * 2];
                    const uint32_t* bw = &bl[nf >> 1][(nf & 1) * 2];
                    mma_f16(acc[mf][nf], ah[mf], bq);   // a*hi
                    mma_f16(acc[mf][nf], ah[mf], bw);   // a*lo
                }
        }
        __syncthreads();
    }

    // ---- epilogue: write g_h + BN partials ----
    float* hb = g_h + (size_t)head * Nv * CC;
    #pragma unroll
    for (int mf = 0; mf < 2; ++mf)
        #pragma unroll
        for (int nf = 0; nf < 4; ++nf) {
            int r = m0 + warpM0 + mf * 16 + (lane >> 2);
            int c = warpN0 + nf * 8 + (lane & 3) * 2;
            float* a = acc[mf][nf];
            if (r < Nv)     *(float2*)(hb + (size_t)r * CC + c)       = make_float2(a[0], a[1]);
            if (r + 8 < Nv) *(float2*)(hb + (size_t)(r + 8) * CC + c) = make_float2(a[2], a[3]);
        }

    float* red = (float*)(smem + SM_RED);   // [4 wm][2 stat][64 col]
    #pragma unroll
    for (int nf = 0; nf < 4; ++nf) {
        float s0 = 0.f, s1 = 0.f, q0 = 0.f, q1 = 0.f;
        #pragma unroll
        for (int mf = 0; mf < 2; ++mf) {
            float* a = acc[mf][nf];
            s0 += a[0] + a[2];  q0 += a[0] * a[0] + a[2] * a[2];
            s1 += a[1] + a[3];  q1 += a[1] * a[1] + a[3] * a[3];
        }
        #pragma unroll
        for (int sh = 4; sh < 32; sh <<= 1) {
            s0 += __shfl_xor_sync(0xffffffffu, s0, sh);
            s1 += __shfl_xor_sync(0xffffffffu, s1, sh);
            q0 += __shfl_xor_sync(0xffffffffu, q0, sh);
            q1 += __shfl_xor_sync(0xffffffffu, q1, sh);
        }
        if (lane < 4) {
            int c = warpN0 + nf * 8 + lane * 2;
            red[(wm * 2 + 0) * 64 + c]     = s0;
            red[(wm * 2 + 0) * 64 + c + 1] = s1;
            red[(wm * 2 + 1) * 64 + c]     = q0;
            red[(wm * 2 + 1) * 64 + c + 1] = q1;
        }
    }
    __syncthreads();
    if (tid < 128) {
        int w = tid >> 6, col = tid & 63;
        float v = red[(0 * 2 + w) * 64 + col] + red[(1 * 2 + w) * 64 + col]
                + red[(2 * 2 + w) * 64 + col] + red[(3 * 2 + w) * 64 + col];
        // transposed: [head][stat][chan][tile] -> coalesced reduce
        g_part[((((size_t)head * 2 + w) * CC) + col) * MAXT + blockIdx.x] = v;
    }
}

// ---------------- BN stats reduce (coalesced over tiles) ----------------
__global__ __launch_bounds__(256) void reduce_stats(
    const float* __restrict__ gamma, const float* __restrict__ beta,
    int Nv, int ntiles)
{
    int gw   = (blockIdx.x * blockDim.x + threadIdx.x) >> 5;
    int lane = threadIdx.x & 31;
    if (gw >= NH * CC) return;
    int head = gw / CC, c = gw % CC;
    const float* ps = g_part + (((size_t)head * 2 + 0) * CC + c) * MAXT;
    const float* pq = g_part + (((size_t)head * 2 + 1) * CC + c) * MAXT;
    float s = 0.f, q = 0.f;
    for (int i = lane; i < ntiles; i += 32) { s += ps[i]; q += pq[i]; }
    #pragma unroll
    for (int sh = 16; sh > 0; sh >>= 1) {
        s += __shfl_down_sync(0xffffffffu, s, sh);
        q += __shfl_down_sync(0xffffffffu, q, sh);
    }
    if (lane == 0) {
        float invN = 1.f / (float)Nv;
        float mean = s * invN;
        float var  = q * invN - mean * mean;
        float inv  = rsqrtf(var + BN_EPS);
        float sc   = inv * gamma[gw];
        g_scale[gw] = sc;
        g_shift[gw] = beta[gw] - mean * sc;
    }
}

// ---------------- pass 2: BN + ReLU + 1x1 convs ----------------
__global__ __launch_bounds__(256) void pass2_kernel(
    const float* __restrict__ W1_0, const float* __restrict__ b1_0,
    const float* __restrict__ W1_1, const float* __restrict__ b1_1,
    const float* __restrict__ W1_2, const float* __restrict__ b1_2,
    const float* __restrict__ W1_3, const float* __restrict__ b1_3,
    const float* __restrict__ W1_4, const float* __restrict__ b1_4,
    float* __restrict__ out, int Nv)
{
    int wid  = (blockIdx.x * blockDim.x + threadIdx.x) >> 5;
    int lane = threadIdx.x & 31;
    if (wid >= NH * Nv) return;
    int head = wid / Nv;
    int n    = wid - head * Nv;

    size_t base = ((size_t)head * Nv + n) * CC;
    int c0 = lane, c1 = lane + 32;
    float h0 = g_h[base + c0];
    float h1 = g_h[base + c1];
    int s0 = head * CC + c0, s1 = head * CC + c1;
    float y0 = fmaxf(0.f, fmaf(h0, g_scale[s0], g_shift[s0]));
    float y1 = fmaxf(0.f, fmaf(h1, g_scale[s1], g_shift[s1]));

    const float* W1; const float* b1; int oc; int off;
    switch (head) {
        case 0:  W1 = W1_0; b1 = b1_0; oc = 3; off = 0; break;
        case 1:  W1 = W1_1; b1 = b1_1; oc = 2; off = 3; break;
        case 2:  W1 = W1_2; b1 = b1_2; oc = 1; off = 5; break;
        case 3:  W1 = W1_3; b1 = b1_3; oc = 3; off = 6; break;
        default: W1 = W1_4; b1 = b1_4; oc = 2; off = 9; break;
    }
    size_t ob = (size_t)off * Nv + (size_t)n * oc;
    for (int o = 0; o < oc; ++o) {
        float p = y0 * W1[c0 * oc + o] + y1 * W1[c1 * oc + o];
        #pragma unroll
        for (int s = 16; s > 0; s >>= 1)
            p += __shfl_down_sync(0xffffffffu, p, s);
        if (lane == 0) out[ob + o] = p + b1[o];
    }
}

// ---------------------------------------------------------------------------
extern "C" void kernel_launch(void* const* d_in, const int* in_sizes, int n_in,
                              void* d_out, int out_size)
{
    const float* feat  = (const float*)d_in[0];
    const int*   nbr   = (const int*)  d_in[1];
    const float* W3    = (const float*)d_in[2];
    const float* gamma = (const float*)d_in[3];
    const float* beta  = (const float*)d_in[4];

    int Nv = in_sizes[0] / CC;
    if (Nv > NMAX) Nv = NMAX;
    int ntiles = (Nv + TMM - 1) / TMM;

    cudaFuncSetAttribute(pass1_mma, cudaFuncAttributeMaxDynamicSharedMemorySize, SM_TOT);

    int nf = Nv * CC;
    prep_feat<<<(nf + 255) / 256, 256>>>(feat, nf);
    prep_w3<<<(NH * KK9 * 4096 + 255) / 256, 256>>>(W3);

    dim3 g1(ntiles, NH);
    pass1_mma<<<g1, 256, SM_TOT>>>(nbr, Nv, ntiles);

    reduce_stats<<<(NH * CC * 32 + 255) / 256, 256>>>(gamma, beta, Nv, ntiles);

    long long nthreads = (long long)NH * Nv * 32;
    int blocks2 = (int)((nthreads + 255) / 256);
    pass2_kernel<<<blocks2, 256>>>(
        (const float*)d_in[5],  (const float*)d_in[6],
        (const float*)d_in[7],  (const float*)d_in[8],
        (const float*)d_in[9],  (const float*)d_in[10],
        (const float*)d_in[11], (const float*)d_in[12],
        (const float*)d_in[13], (const float*)d_in[14],
        (float*)d_out, Nv);
}

// round 6
// speedup vs baseline: 4.2137x; 1.2712x over previous
#include <cuda_runtime.h>
#include <cuda_fp16.h>
#include <cstdint>

#define CC     64
#define KK9    9
#define NH     5
#define NMAX   150000
#define TMM    128
#define MAXT   ((NMAX + TMM - 1) / TMM)     // 1172
#define BN_EPS 1e-5f

// ---------------- device global scratch (no allocations allowed) ----------------
__device__ __half g_f16[(size_t)NMAX * CC];                    // features (fp16)
__device__ __half g_B16[(size_t)NH * KK9 * 4096];              // weights fp16, swizzled
__device__ float g_h[(size_t)NH * NMAX * CC];                  // 192 MB intermediate
__device__ float g_part[(size_t)NH * 2 * CC * MAXT];           // [head][stat][chan][tile]
__device__ float g_scale[NH * CC];
__device__ float g_shift[NH * CC];

// ---------------- helpers ----------------
__device__ __forceinline__ uint32_t smem_u32(const void* p) {
    uint32_t a;
    asm("{ .reg .u64 t; cvta.to.shared.u64 t, %1; cvt.u32.u64 %0, t; }" : "=r"(a) : "l"(p));
    return a;
}
__device__ __forceinline__ void cpa16(uint32_t dst, const void* src, uint32_t sz) {
    asm volatile("cp.async.cg.shared.global [%0], [%1], 16, %2;"
                 :: "r"(dst), "l"(src), "r"(sz) : "memory");
}
__device__ __forceinline__ void cpa_commit() {
    asm volatile("cp.async.commit_group;" ::: "memory");
}
__device__ __forceinline__ void ldx4(uint32_t* r, uint32_t addr) {
    asm volatile("ldmatrix.sync.aligned.m8n8.x4.shared.b16 {%0,%1,%2,%3}, [%4];"
                 : "=r"(r[0]), "=r"(r[1]), "=r"(r[2]), "=r"(r[3]) : "r"(addr));
}
__device__ __forceinline__ void mma_f16(float* c, const uint32_t* a, const uint32_t* b) {
    asm volatile(
        "mma.sync.aligned.m16n8k16.row.col.f32.f16.f16.f32 "
        "{%0,%1,%2,%3}, {%4,%5,%6,%7}, {%8,%9}, {%0,%1,%2,%3};"
        : "+f"(c[0]), "+f"(c[1]), "+f"(c[2]), "+f"(c[3])
        : "r"(a[0]), "r"(a[1]), "r"(a[2]), "r"(a[3]), "r"(b[0]), "r"(b[1]));
}

// ---------------- prep kernels ----------------
__global__ __launch_bounds__(256) void prep_feat(const float* __restrict__ f, int n) {
    int i = blockIdx.x * blockDim.x + threadIdx.x;
    if (i >= n) return;
    g_f16[i] = __float2half(f[i]);
}

// W3 [h][k][c][o] -> slabs [h*9+k][n=o][k=c] fp16, 16B-xor swizzled for ldmatrix
__global__ __launch_bounds__(256) void prep_w3(const float* __restrict__ w) {
    int i = blockIdx.x * blockDim.x + threadIdx.x;
    if (i >= NH * KK9 * 4096) return;
    int slab = i >> 12;
    int r = i & 4095;
    int c = r >> 6;        // K index
    int o = r & 63;        // N index
    int e = (o * 8 + ((c >> 3) ^ (o & 7))) * 8 + (c & 7);
    g_B16[(size_t)slab * 4096 + e] = __float2half(w[i]);
}

// ---------------- pass1: fp16 mma.sync gather-GEMM ----------------
// SMEM: A: 2 stages x 16KB = 32KB at 0
//       B: 2 stages x 8KB  = 16KB at 32768
//       red: 4 x 2 x 64 floats = 2KB at 49152
#define SM_A    0u
#define SM_B    32768u
#define SM_RED  49152u
#define SM_TOT  (SM_RED + 2048u)

__device__ __forceinline__ void gatherA(uint32_t sb, int stage,
                                        const int* __restrict__ nbr,
                                        int m0, int Nv, int k)
{
    const int t   = threadIdx.x;
    const int row = t >> 1;          // 128 rows, 2 threads each
    const int m   = m0 + row;
    int idx = -1;
    if (m < Nv) idx = __ldg(&nbr[(size_t)m * KK9 + k]);
    uint32_t sz = (idx >= 0) ? 16u : 0u;
    int ic = (idx >= 0) ? idx : 0;
    const char* src = (const char*)g_f16 + (size_t)ic * 128 + (t & 1) * 64;
    uint32_t dbase = sb + SM_A + (uint32_t)stage * 16384u + (uint32_t)row * 128u;
    #pragma unroll
    for (int j = 0; j < 4; ++j) {
        int c16 = (t & 1) * 4 + j;
        uint32_t off = (uint32_t)((c16 ^ (row & 7)) << 4);
        cpa16(dbase + off, src + j * 16, sz);
    }
}

__device__ __forceinline__ void copyB(uint32_t sb, int stage, int slab) {
    const int t = threadIdx.x;
    const char* src = (const char*)g_B16 + (size_t)slab * 8192;
    uint32_t dst = sb + SM_B + (uint32_t)stage * 8192u;
    #pragma unroll
    for (int j = 0; j < 2; ++j) {
        int i = t + j * 256;
        cpa16(dst + (uint32_t)i * 16u, src + (size_t)i * 16, 16u);
    }
}

__global__ __launch_bounds__(256, 3) void pass1_mma(
    const int* __restrict__ nbr, int Nv, int ntiles)
{
    extern __shared__ char smem[];
    const uint32_t sb = smem_u32(smem);
    const int tid  = threadIdx.x;
    const int wid  = tid >> 5;
    const int lane = tid & 31;
    const int m0   = blockIdx.x * TMM;
    const int head = blockIdx.y;

    const int wm = wid & 3;            // 4 M-warps (32 rows each)
    const int wn = wid >> 2;           // 2 N-warps (32 cols each)
    const int warpM0 = wm * 32;
    const int warpN0 = wn * 32;

    float acc[2][4][4];                // [mf][nf][4]
    #pragma unroll
    for (int i = 0; i < 2; ++i)
        #pragma unroll
        for (int j = 0; j < 4; ++j)
            #pragma unroll
            for (int q = 0; q < 4; ++q) acc[i][j][q] = 0.f;

    // prologue
    gatherA(sb, 0, nbr, m0, Nv, 0);
    copyB(sb, 0, head * KK9 + 0);
    cpa_commit();

    for (int k = 0; k < KK9; ++k) {
        const int stage = k & 1;
        if (k + 1 < KK9) {
            gatherA(sb, stage ^ 1, nbr, m0, Nv, k + 1);
            copyB(sb, stage ^ 1, head * KK9 + k + 1);
            cpa_commit();
            asm volatile("cp.async.wait_group 1;" ::: "memory");
        } else {
            asm volatile("cp.async.wait_group 0;" ::: "memory");
        }
        __syncthreads();

        const uint32_t Ah = sb + SM_A + (uint32_t)stage * 16384u;
        const uint32_t Bh = sb + SM_B + (uint32_t)stage * 8192u;

        #pragma unroll
        for (int kk = 0; kk < 4; ++kk) {
            uint32_t ah[2][4];
            #pragma unroll
            for (int mf = 0; mf < 2; ++mf) {
                int rr = warpM0 + mf * 16 + (lane & 7) + ((lane >> 3) & 1) * 8;
                int c16 = kk * 2 + (lane >> 4);
                uint32_t byte = (uint32_t)(rr * 128 + ((c16 ^ (rr & 7)) << 4));
                ldx4(ah[mf], Ah + byte);
            }
            uint32_t bh[2][4];             // [pair p: nf {2p,2p+1}]
            #pragma unroll
            for (int p = 0; p < 2; ++p) {
                int nn = warpN0 + p * 16 + (lane & 7) + ((lane >> 4) << 3);
                int c16 = kk * 2 + ((lane >> 3) & 1);
                uint32_t byte = (uint32_t)(nn * 128 + ((c16 ^ (nn & 7)) << 4));
                ldx4(bh[p], Bh + byte);
            }
            #pragma unroll
            for (int mf = 0; mf < 2; ++mf)
                #pragma unroll
                for (int nf = 0; nf < 4; ++nf)
                    mma_f16(acc[mf][nf], ah[mf], &bh[nf >> 1][(nf & 1) * 2]);
        }
        __syncthreads();
    }

    // ---- epilogue: write g_h + BN partials ----
    float* hb = g_h + (size_t)head * Nv * CC;
    #pragma unroll
    for (int mf = 0; mf < 2; ++mf)
        #pragma unroll
        for (int nf = 0; nf < 4; ++nf) {
            int r = m0 + warpM0 + mf * 16 + (lane >> 2);
            int c = warpN0 + nf * 8 + (lane & 3) * 2;
            float* a = acc[mf][nf];
            if (r < Nv)     *(float2*)(hb + (size_t)r * CC + c)       = make_float2(a[0], a[1]);
            if (r + 8 < Nv) *(float2*)(hb + (size_t)(r + 8) * CC + c) = make_float2(a[2], a[3]);
        }

    float* red = (float*)(smem + SM_RED);   // [4 wm][2 stat][64 col]
    #pragma unroll
    for (int nf = 0; nf < 4; ++nf) {
        float s0 = 0.f, s1 = 0.f, q0 = 0.f, q1 = 0.f;
        #pragma unroll
        for (int mf = 0; mf < 2; ++mf) {
            float* a = acc[mf][nf];
            s0 += a[0] + a[2];  q0 += a[0] * a[0] + a[2] * a[2];
            s1 += a[1] + a[3];  q1 += a[1] * a[1] + a[3] * a[3];
        }
        #pragma unroll
        for (int sh = 4; sh < 32; sh <<= 1) {
            s0 += __shfl_xor_sync(0xffffffffu, s0, sh);
            s1 += __shfl_xor_sync(0xffffffffu, s1, sh);
            q0 += __shfl_xor_sync(0xffffffffu, q0, sh);
            q1 += __shfl_xor_sync(0xffffffffu, q1, sh);
        }
        if (lane < 4) {
            int c = warpN0 + nf * 8 + lane * 2;
            red[(wm * 2 + 0) * 64 + c]     = s0;
            red[(wm * 2 + 0) * 64 + c + 1] = s1;
            red[(wm * 2 + 1) * 64 + c]     = q0;
            red[(wm * 2 + 1) * 64 + c + 1] = q1;
        }
    }
    __syncthreads();
    if (tid < 128) {
        int w = tid >> 6, col = tid & 63;
        float v = red[(0 * 2 + w) * 64 + col] + red[(1 * 2 + w) * 64 + col]
                + red[(2 * 2 + w) * 64 + col] + red[(3 * 2 + w) * 64 + col];
        // transposed: [head][stat][chan][tile] -> coalesced reduce
        g_part[((((size_t)head * 2 + w) * CC) + col) * MAXT + blockIdx.x] = v;
    }
}

// ---------------- BN stats reduce (coalesced + vectorized over tiles) ----------------
__global__ __launch_bounds__(256) void reduce_stats(
    const float* __restrict__ gamma, const float* __restrict__ beta,
    int Nv, int ntiles)
{
    int gw   = (blockIdx.x * blockDim.x + threadIdx.x) >> 5;
    int lane = threadIdx.x & 31;
    if (gw >= NH * CC) return;
    int head = gw / CC, c = gw % CC;
    const float* ps = g_part + (((size_t)head * 2 + 0) * CC + c) * MAXT;
    const float* pq = g_part + (((size_t)head * 2 + 1) * CC + c) * MAXT;
    float s = 0.f, q = 0.f;
    int nt4 = ntiles >> 2;
    const float4* ps4 = (const float4*)ps;
    const float4* pq4 = (const float4*)pq;
    for (int i = lane; i < nt4; i += 32) {
        float4 a = ps4[i], b = pq4[i];
        s += (a.x + a.y) + (a.z + a.w);
        q += (b.x + b.y) + (b.z + b.w);
    }
    for (int i = nt4 * 4 + lane; i < ntiles; i += 32) { s += ps[i]; q += pq[i]; }
    #pragma unroll
    for (int sh = 16; sh > 0; sh >>= 1) {
        s += __shfl_down_sync(0xffffffffu, s, sh);
        q += __shfl_down_sync(0xffffffffu, q, sh);
    }
    if (lane == 0) {
        float invN = 1.f / (float)Nv;
        float mean = s * invN;
        float var  = q * invN - mean * mean;
        float inv  = rsqrtf(var + BN_EPS);
        float sc   = inv * gamma[gw];
        g_scale[gw] = sc;
        g_shift[gw] = beta[gw] - mean * sc;
    }
}

// ---------------- pass 2: BN + ReLU + 1x1 convs ----------------
__global__ __launch_bounds__(256) void pass2_kernel(
    const float* __restrict__ W1_0, const float* __restrict__ b1_0,
    const float* __restrict__ W1_1, const float* __restrict__ b1_1,
    const float* __restrict__ W1_2, const float* __restrict__ b1_2,
    const float* __restrict__ W1_3, const float* __restrict__ b1_3,
    const float* __restrict__ W1_4, const float* __restrict__ b1_4,
    float* __restrict__ out, int Nv)
{
    int wid  = (blockIdx.x * blockDim.x + threadIdx.x) >> 5;
    int lane = threadIdx.x & 31;
    if (wid >= NH * Nv) return;
    int head = wid / Nv;
    int n    = wid - head * Nv;

    size_t base = ((size_t)head * Nv + n) * CC;
    int c0 = lane, c1 = lane + 32;
    float h0 = g_h[base + c0];
    float h1 = g_h[base + c1];
    int s0 = head * CC + c0, s1 = head * CC + c1;
    float y0 = fmaxf(0.f, fmaf(h0, g_scale[s0], g_shift[s0]));
    float y1 = fmaxf(0.f, fmaf(h1, g_scale[s1], g_shift[s1]));

    const float* W1; const float* b1; int oc; int off;
    switch (head) {
        case 0:  W1 = W1_0; b1 = b1_0; oc = 3; off = 0; break;
        case 1:  W1 = W1_1; b1 = b1_1; oc = 2; off = 3; break;
        case 2:  W1 = W1_2; b1 = b1_2; oc = 1; off = 5; break;
        case 3:  W1 = W1_3; b1 = b1_3; oc = 3; off = 6; break;
        default: W1 = W1_4; b1 = b1_4; oc = 2; off = 9; break;
    }
    size_t ob = (size_t)off * Nv + (size_t)n * oc;
    for (int o = 0; o < oc; ++o) {
        float p = y0 * W1[c0 * oc + o] + y1 * W1[c1 * oc + o];
        #pragma unroll
        for (int s = 16; s > 0; s >>= 1)
            p += __shfl_down_sync(0xffffffffu, p, s);
        if (lane == 0) out[ob + o] = p + b1[o];
    }
}

// ---------------------------------------------------------------------------
extern "C" void kernel_launch(void* const* d_in, const int* in_sizes, int n_in,
                              void* d_out, int out_size)
{
    const float* feat  = (const float*)d_in[0];
    const int*   nbr   = (const int*)  d_in[1];
    const float* W3    = (const float*)d_in[2];
    const float* gamma = (const float*)d_in[3];
    const float* beta  = (const float*)d_in[4];

    int Nv = in_sizes[0] / CC;
    if (Nv > NMAX) Nv = NMAX;
    int ntiles = (Nv + TMM - 1) / TMM;

    cudaFuncSetAttribute(pass1_mma, cudaFuncAttributeMaxDynamicSharedMemorySize, SM_TOT);

    int nf = Nv * CC;
    prep_feat<<<(nf + 255) / 256, 256>>>(feat, nf);
    prep_w3<<<(NH * KK9 * 4096 + 255) / 256, 256>>>(W3);

    dim3 g1(ntiles, NH);
    pass1_mma<<<g1, 256, SM_TOT>>>(nbr, Nv, ntiles);

    reduce_stats<<<(NH * CC * 32 + 255) / 256, 256>>>(gamma, beta, Nv, ntiles);

    long long nthreads = (long long)NH * Nv * 32;
    int blocks2 = (int)((nthreads + 255) / 256);
    pass2_kernel<<<blocks2, 256>>>(
        (const float*)d_in[5],  (const float*)d_in[6],
        (const float*)d_in[7],  (const float*)d_in[8],
        (const float*)d_in[9],  (const float*)d_in[10],
        (const float*)d_in[11], (const float*)d_in[12],
        (const float*)d_in[13], (const float*)d_in[14],
        (float*)d_out, Nv);
}